// round 12
// baseline (speedup 1.0000x reference)
#include <cuda_runtime.h>
#include <cuda_fp16.h>
#include <math.h>

#define NN 50000
#define EE 800000
#define ETOT 850000
#define IND 128
#define F1 256
#define H1N 4
#define F2 64
#define SCAN_BLOCKS 196

// ---------------- scratch (device globals; no allocation allowed) ----------------
__device__ __align__(16) __half g_lin1h[(size_t)NN * F1];
__device__ __align__(16) __half g_h1h[(size_t)NN * F1];
__device__ __align__(16) __half g_lin2h[(size_t)NN * F2];
__device__ __align__(16) __half g_h2h[(size_t)NN * F2];
__device__ float g_as1[NN * H1N], g_ad1[NN * H1N];
__device__ float g_as2[NN], g_ad2[NN];
__device__ int g_deg[NN], g_off[NN + 1], g_pos[NN], g_csr[ETOT];
__device__ int g_bsum[SCAN_BLOCKS];
__device__ float g_sum1[F1], g_sq1[F1], g_sum2[F2], g_sq2[F2], g_sum3[IND], g_sq3[IND];

// ---------------- helpers ----------------
__device__ __forceinline__ float elu_f(float v) { return v > 0.f ? v : expm1f(v); }

// bf16 hi/lo split of two floats, packed as bf16x2 (f0 -> low half, f1 -> high half)
__device__ __forceinline__ void split2_bf16(float f0, float f1, unsigned& hi, unsigned& lo) {
    asm("cvt.rn.bf16x2.f32 %0, %1, %2;" : "=r"(hi) : "f"(f1), "f"(f0));
    float h0 = __uint_as_float(hi << 16);
    float h1 = __uint_as_float(hi & 0xffff0000u);
    float r0 = f0 - h0, r1 = f1 - h1;
    asm("cvt.rn.bf16x2.f32 %0, %1, %2;" : "=r"(lo) : "f"(r1), "f"(r0));
}

__device__ __forceinline__ void mma_bf16(float* c, const unsigned* a, const unsigned* b) {
    asm volatile(
        "mma.sync.aligned.m16n8k16.row.col.f32.bf16.bf16.f32 "
        "{%0,%1,%2,%3},{%4,%5,%6,%7},{%8,%9},{%0,%1,%2,%3};"
        : "+f"(c[0]), "+f"(c[1]), "+f"(c[2]), "+f"(c[3])
        : "r"(a[0]), "r"(a[1]), "r"(a[2]), "r"(a[3]), "r"(b[0]), "r"(b[1]));
}

__device__ __forceinline__ void edge_sd(const int* ei, int e, int& s, int& d) {
    if (e < EE) { s = ei[e]; d = ei[EE + e]; } else { s = d = e - EE; }
}

// ---------------- init ----------------
__global__ void zero_k() {
    int i = blockIdx.x * 256 + threadIdx.x;
    if (i < NN) g_deg[i] = 0;
    if (blockIdx.x == 0) {
        int t = threadIdx.x;
        if (t < F1) { g_sum1[t] = 0.f; g_sq1[t] = 0.f; }
        if (t < F2) { g_sum2[t] = 0.f; g_sq2[t] = 0.f; }
        if (t < IND) { g_sum3[t] = 0.f; g_sq3[t] = 0.f; }
    }
}

// ---------------- counting sort: hist -> scan -> scatter ----------------
__global__ void hist_k(const int* __restrict__ ei) {
    int e = blockIdx.x * blockDim.x + threadIdx.x;
    if (e >= ETOT) return;
    int s, d; edge_sd(ei, e, s, d);
    atomicAdd(&g_deg[d], 1);
}

__global__ void scan_part() {
    __shared__ int sm[256];
    int t = threadIdx.x;
    int i = blockIdx.x * 256 + t;
    int v = (i < NN) ? g_deg[i] : 0;
    sm[t] = v; __syncthreads();
    #pragma unroll
    for (int off = 1; off < 256; off <<= 1) {
        int x = (t >= off) ? sm[t - off] : 0;
        __syncthreads();
        sm[t] += x; __syncthreads();
    }
    if (i < NN) g_off[i] = sm[t];
    if (t == 255) g_bsum[blockIdx.x] = sm[255];
}

__global__ void scan_fix2() {
    __shared__ int sb[256];
    int t = threadIdx.x;
    sb[t] = (t < SCAN_BLOCKS) ? g_bsum[t] : 0;
    __syncthreads();
    #pragma unroll
    for (int off = 1; off < 256; off <<= 1) {
        int x = (t >= off) ? sb[t - off] : 0;
        __syncthreads();
        sb[t] += x; __syncthreads();
    }
    int base = (blockIdx.x == 0) ? 0 : sb[blockIdx.x - 1];
    int i = blockIdx.x * 256 + t;
    if (i < NN) {
        int off = g_off[i] - g_deg[i] + base;
        g_off[i] = off;
        g_pos[i] = off;
    }
    if (i == 0) g_off[NN] = ETOT;
}

__global__ void scatter_k(const int* __restrict__ ei) {
    int e = blockIdx.x * blockDim.x + threadIdx.x;
    if (e >= ETOT) return;
    int s, d; edge_sd(ei, e, s, d);
    int p = atomicAdd(&g_pos[d], 1);
    g_csr[p] = s;
}

// ---------------- bf16x3 tensor-core GEMM, NP column panels per block ----------------
// hi/lo tiles interleaved as uint2 -> ONE LDS.64 per fragment pair (halves LDS count).
// A row stride 20 uint2 (bank = 4g+tg, conflict-free); B row stride 68 uint2 (bank = 4tg+g).
template<int NP, bool PRE_BN, bool BIAS, bool ALPHA, bool BNSTAT, bool HALF_IN, bool HALF_OUT>
__global__ void __launch_bounds__(256)
gemm_bf16(const void* __restrict__ Av, const float* __restrict__ B,
          const float* __restrict__ bias,
          const float* __restrict__ psum, const float* __restrict__ psq,
          const float* __restrict__ pgamma, const float* __restrict__ pbeta,
          const float* __restrict__ avs, const float* __restrict__ avd,
          float* __restrict__ as_out, float* __restrict__ ad_out,
          float* __restrict__ bnsum_out, float* __restrict__ bnsq_out,
          void* __restrict__ Cv, int M, int N, int K)
{
    const int BM = 128, BN = 64, BK = 32, BKP = 16;
    const int ASTR = 20;   // uint2 stride for A rows (== 4 mod 16)
    const int BSTR = 68;   // uint2 stride for B rows (== 4 mod 16)
    __shared__ __align__(16) uint2 Aab[BM][ASTR];
    __shared__ __align__(16) uint2 Bab[NP][BKP][BSTR];
    __shared__ float s_sc[256], s_sh[256];
    __shared__ float s_as[NP * BM], s_ad[NP * BM];
    __shared__ float s_bs[NP * BN], s_bq[NP * BN];
    int tid = threadIdx.x;
    int lane = tid & 31, wid = tid >> 5;
    int wm = wid & 3, wn = wid >> 2;
    int row0 = blockIdx.y * BM;
    int colBase = blockIdx.x * (NP * BN);
    int g = lane >> 2, tg = lane & 3;

    if (PRE_BN) {
        if (tid < K) {
            float mean = psum[tid] * (1.0f / NN);
            float var = fmaxf(psq[tid] * (1.0f / NN) - mean * mean, 0.f);
            float sc = pgamma[tid] * rsqrtf(var + 1e-5f);
            s_sc[tid] = sc;
            s_sh[tid] = pbeta[tid] - mean * sc;
        }
        __syncthreads();
    }
    if (ALPHA) {
        #pragma unroll
        for (int p = 0; p < NP; p++)
            if (tid < BM) { s_as[p * BM + tid] = 0.f; s_ad[p * BM + tid] = 0.f; }
    }
    if (BNSTAT && tid < NP * BN) { s_bs[tid] = 0.f; s_bq[tid] = 0.f; }

    float c[NP][2][4][4];
    #pragma unroll
    for (int p = 0; p < NP; p++)
        #pragma unroll
        for (int mt = 0; mt < 2; mt++)
            #pragma unroll
            for (int nt = 0; nt < 4; nt++)
                #pragma unroll
                for (int j = 0; j < 4; j++) c[p][mt][nt][j] = 0.f;

    for (int k0 = 0; k0 < K; k0 += BK) {
        // ---- A tile: load + (optional BN/ELU) + bf16 split, hi/lo interleaved ----
        if (HALF_IN) {
            const __half* Ahp = (const __half*)Av;
            #pragma unroll
            for (int i = 0; i < 2; i++) {
                int idx = i * 256 + tid;
                int r = idx >> 2, q = idx & 3;
                uint4 raw = make_uint4(0u, 0u, 0u, 0u);
                if (row0 + r < M)
                    raw = *(const uint4*)(Ahp + (size_t)(row0 + r) * K + k0 + q * 8);
                float f[8];
                float2 t2;
                t2 = __half22float2(*(__half2*)&raw.x); f[0] = t2.x; f[1] = t2.y;
                t2 = __half22float2(*(__half2*)&raw.y); f[2] = t2.x; f[3] = t2.y;
                t2 = __half22float2(*(__half2*)&raw.z); f[4] = t2.x; f[5] = t2.y;
                t2 = __half22float2(*(__half2*)&raw.w); f[6] = t2.x; f[7] = t2.y;
                if (PRE_BN) {
                    int b = k0 + q * 8;
                    #pragma unroll
                    for (int j = 0; j < 8; j++) f[j] = elu_f(f[j] * s_sc[b + j] + s_sh[b + j]);
                }
                #pragma unroll
                for (int j = 0; j < 4; j++) {
                    unsigned hi, lo;
                    split2_bf16(f[j * 2], f[j * 2 + 1], hi, lo);
                    Aab[r][q * 4 + j] = make_uint2(hi, lo);
                }
            }
        } else {
            const float* Af = (const float*)Av;
            #pragma unroll
            for (int i = 0; i < 4; i++) {
                int idx = i * 256 + tid;
                int r = idx >> 3, q = idx & 7;
                float4 v = make_float4(0.f, 0.f, 0.f, 0.f);
                if (row0 + r < M)
                    v = *(const float4*)(Af + (size_t)(row0 + r) * K + k0 + q * 4);
                if (PRE_BN) {
                    int b = k0 + q * 4;
                    v.x = elu_f(v.x * s_sc[b + 0] + s_sh[b + 0]);
                    v.y = elu_f(v.y * s_sc[b + 1] + s_sh[b + 1]);
                    v.z = elu_f(v.z * s_sc[b + 2] + s_sh[b + 2]);
                    v.w = elu_f(v.w * s_sc[b + 3] + s_sh[b + 3]);
                }
                unsigned h0, l0, h1, l1;
                split2_bf16(v.x, v.y, h0, l0);
                split2_bf16(v.z, v.w, h1, l1);
                Aab[r][q * 2 + 0] = make_uint2(h0, l0);
                Aab[r][q * 2 + 1] = make_uint2(h1, l1);
            }
        }
        // ---- B tiles for all NP panels ----
        {
            int kp = tid >> 4;
            int cq = (tid & 15) * 4;
            #pragma unroll
            for (int p = 0; p < NP; p++) {
                int cb = colBase + p * BN + cq;
                float4 v0 = *(const float4*)(B + (size_t)(k0 + 2 * kp) * N + cb);
                float4 v1 = *(const float4*)(B + (size_t)(k0 + 2 * kp + 1) * N + cb);
                unsigned h, l;
                split2_bf16(v0.x, v1.x, h, l); Bab[p][kp][cq + 0] = make_uint2(h, l);
                split2_bf16(v0.y, v1.y, h, l); Bab[p][kp][cq + 1] = make_uint2(h, l);
                split2_bf16(v0.z, v1.z, h, l); Bab[p][kp][cq + 2] = make_uint2(h, l);
                split2_bf16(v0.w, v1.w, h, l); Bab[p][kp][cq + 3] = make_uint2(h, l);
            }
        }
        __syncthreads();

        #pragma unroll
        for (int kk = 0; kk < 2; kk++) {
            unsigned ahi[2][4], alo[2][4];
            #pragma unroll
            for (int mt = 0; mt < 2; mt++) {
                int rb = wm * 32 + mt * 16 + g;
                int kp = kk * 8 + tg;
                uint2 a0 = Aab[rb][kp];
                uint2 a1 = Aab[rb + 8][kp];
                uint2 a2 = Aab[rb][kp + 4];
                uint2 a3 = Aab[rb + 8][kp + 4];
                ahi[mt][0] = a0.x; alo[mt][0] = a0.y;
                ahi[mt][1] = a1.x; alo[mt][1] = a1.y;
                ahi[mt][2] = a2.x; alo[mt][2] = a2.y;
                ahi[mt][3] = a3.x; alo[mt][3] = a3.y;
            }
            #pragma unroll
            for (int p = 0; p < NP; p++) {
                unsigned bhi[4][2], blo[4][2];
                #pragma unroll
                for (int nt = 0; nt < 4; nt++) {
                    int cb = wn * 32 + nt * 8 + g;
                    int kp = kk * 8 + tg;
                    uint2 b0 = Bab[p][kp][cb];
                    uint2 b1 = Bab[p][kp + 4][cb];
                    bhi[nt][0] = b0.x; blo[nt][0] = b0.y;
                    bhi[nt][1] = b1.x; blo[nt][1] = b1.y;
                }
                #pragma unroll
                for (int mt = 0; mt < 2; mt++)
                    #pragma unroll
                    for (int nt = 0; nt < 4; nt++) {
                        mma_bf16(c[p][mt][nt], ahi[mt], blo[nt]);
                        mma_bf16(c[p][mt][nt], alo[mt], bhi[nt]);
                        mma_bf16(c[p][mt][nt], ahi[mt], bhi[nt]);
                    }
            }
        }
        __syncthreads();
    }

    float* Cf = (float*)Cv;
    __half* Ch = (__half*)Cv;

    #pragma unroll
    for (int p = 0; p < NP; p++) {
        float pas[2][2], pad[2][2];
        float colsum[8], colsq[8];
        if (ALPHA) {
            #pragma unroll
            for (int a = 0; a < 2; a++)
                #pragma unroll
                for (int b = 0; b < 2; b++) { pas[a][b] = 0.f; pad[a][b] = 0.f; }
        }
        if (BNSTAT) {
            #pragma unroll
            for (int j = 0; j < 8; j++) { colsum[j] = 0.f; colsq[j] = 0.f; }
        }

        #pragma unroll
        for (int mt = 0; mt < 2; mt++)
            #pragma unroll
            for (int nt = 0; nt < 4; nt++) {
                int r = row0 + wm * 32 + mt * 16 + g;
                int cc = colBase + p * BN + wn * 32 + nt * 8 + tg * 2;
                float v00 = c[p][mt][nt][0], v01 = c[p][mt][nt][1];
                float v10 = c[p][mt][nt][2], v11 = c[p][mt][nt][3];
                if (BIAS) {
                    float bx = bias[cc], by = bias[cc + 1];
                    v00 += bx; v01 += by; v10 += bx; v11 += by;
                }
                if (ALPHA) {
                    float s0 = avs[cc], s1 = avs[cc + 1];
                    float d0 = avd[cc], d1 = avd[cc + 1];
                    pas[mt][0] += v00 * s0 + v01 * s1;
                    pad[mt][0] += v00 * d0 + v01 * d1;
                    pas[mt][1] += v10 * s0 + v11 * s1;
                    pad[mt][1] += v10 * d0 + v11 * d1;
                }
                if (BNSTAT) {
                    if (r < M)     { colsum[nt * 2] += v00; colsq[nt * 2] += v00 * v00;
                                     colsum[nt * 2 + 1] += v01; colsq[nt * 2 + 1] += v01 * v01; }
                    if (r + 8 < M) { colsum[nt * 2] += v10; colsq[nt * 2] += v10 * v10;
                                     colsum[nt * 2 + 1] += v11; colsq[nt * 2 + 1] += v11 * v11; }
                }
                if (HALF_OUT) {
                    if (r < M)     *(__half2*)(Ch + (size_t)r * N + cc) = __floats2half2_rn(v00, v01);
                    if (r + 8 < M) *(__half2*)(Ch + (size_t)(r + 8) * N + cc) = __floats2half2_rn(v10, v11);
                } else {
                    if (r < M)     *(float2*)(Cf + (size_t)r * N + cc) = make_float2(v00, v01);
                    if (r + 8 < M) *(float2*)(Cf + (size_t)(r + 8) * N + cc) = make_float2(v10, v11);
                }
            }

        if (ALPHA) {
            #pragma unroll
            for (int mt = 0; mt < 2; mt++)
                #pragma unroll
                for (int ro = 0; ro < 2; ro++) {
                    float vs = pas[mt][ro], vd = pad[mt][ro];
                    vs += __shfl_down_sync(0xffffffffu, vs, 2);
                    vs += __shfl_down_sync(0xffffffffu, vs, 1);
                    vd += __shfl_down_sync(0xffffffffu, vd, 2);
                    vd += __shfl_down_sync(0xffffffffu, vd, 1);
                    if (tg == 0) {
                        int rl = wm * 32 + mt * 16 + ro * 8 + g;
                        atomicAdd(&s_as[p * BM + rl], vs);
                        atomicAdd(&s_ad[p * BM + rl], vd);
                    }
                }
        }
        if (BNSTAT) {
            #pragma unroll
            for (int j = 0; j < 8; j++) {
                float v = colsum[j], q = colsq[j];
                v += __shfl_down_sync(0xffffffffu, v, 16);
                v += __shfl_down_sync(0xffffffffu, v, 8);
                v += __shfl_down_sync(0xffffffffu, v, 4);
                q += __shfl_down_sync(0xffffffffu, q, 16);
                q += __shfl_down_sync(0xffffffffu, q, 8);
                q += __shfl_down_sync(0xffffffffu, q, 4);
                if (lane < 4) {
                    int cb = wn * 32 + (j >> 1) * 8 + tg * 2 + (j & 1);
                    atomicAdd(&s_bs[p * BN + cb], v);
                    atomicAdd(&s_bq[p * BN + cb], q);
                }
            }
        }
    }
    if (ALPHA || BNSTAT) {
        __syncthreads();
        if (ALPHA && tid < BM) {
            int r = row0 + tid;
            if (r < M) {
                int nh = gridDim.x * NP;
                #pragma unroll
                for (int p = 0; p < NP; p++) {
                    as_out[(size_t)r * nh + blockIdx.x * NP + p] = s_as[p * BM + tid];
                    ad_out[(size_t)r * nh + blockIdx.x * NP + p] = s_ad[p * BM + tid];
                }
            }
        }
        if (BNSTAT && tid < NP * BN) {
            atomicAdd(&bnsum_out[colBase + tid], s_bs[tid]);
            atomicAdd(&bnsq_out[colBase + tid], s_bq[tid]);
        }
    }
}

// ---------------- CSR aggregation (softmax + weighted sum + bias + BN stats) ----------------
__device__ __forceinline__ void acc_row1(float* acc, const uint4& raw, float w) {
    float2 f;
    f = __half22float2(*(__half2*)&raw.x); acc[0] += w * f.x; acc[1] += w * f.y;
    f = __half22float2(*(__half2*)&raw.y); acc[2] += w * f.x; acc[3] += w * f.y;
    f = __half22float2(*(__half2*)&raw.z); acc[4] += w * f.x; acc[5] += w * f.y;
    f = __half22float2(*(__half2*)&raw.w); acc[6] += w * f.x; acc[7] += w * f.y;
}

__global__ void __launch_bounds__(256) agg1_csr(const float* __restrict__ b1) {
    int lane = threadIdx.x & 31;
    int wid = threadIdx.x >> 5;
    int gw = blockIdx.x * 8 + wid;
    int nw = gridDim.x * 8;
    int h = lane >> 3;
    float lsum[8], lsq[8];
    #pragma unroll
    for (int j = 0; j < 8; j++) { lsum[j] = 0.f; lsq[j] = 0.f; }

    for (int dst = gw; dst < NN; dst += nw) {
        int beg = g_off[dst], end = g_off[dst + 1];
        float ad = g_ad1[dst * 4 + h];
        float acc[8];
        #pragma unroll
        for (int j = 0; j < 8; j++) acc[j] = 0.f;
        float den = 0.f;
        int e = beg;
        for (; e + 3 < end; e += 4) {
            int s0 = g_csr[e], s1 = g_csr[e + 1], s2 = g_csr[e + 2], s3 = g_csr[e + 3];
            float ev0 = g_as1[s0 * 4 + h] + ad;
            float ev1 = g_as1[s1 * 4 + h] + ad;
            float ev2 = g_as1[s2 * 4 + h] + ad;
            float ev3 = g_as1[s3 * 4 + h] + ad;
            ev0 = fmaxf(ev0, 0.2f * ev0);
            ev1 = fmaxf(ev1, 0.2f * ev1);
            ev2 = fmaxf(ev2, 0.2f * ev2);
            ev3 = fmaxf(ev3, 0.2f * ev3);
            float w0 = __expf(ev0), w1 = __expf(ev1), w2 = __expf(ev2), w3 = __expf(ev3);
            den += (w0 + w1) + (w2 + w3);
            uint4 r0 = *((const uint4*)(g_lin1h + (size_t)s0 * F1) + lane);
            uint4 r1 = *((const uint4*)(g_lin1h + (size_t)s1 * F1) + lane);
            uint4 r2 = *((const uint4*)(g_lin1h + (size_t)s2 * F1) + lane);
            uint4 r3 = *((const uint4*)(g_lin1h + (size_t)s3 * F1) + lane);
            acc_row1(acc, r0, w0); acc_row1(acc, r1, w1);
            acc_row1(acc, r2, w2); acc_row1(acc, r3, w3);
        }
        for (; e < end; e++) {
            int s0 = g_csr[e];
            float ev0 = g_as1[s0 * 4 + h] + ad;
            ev0 = fmaxf(ev0, 0.2f * ev0);
            float w0 = __expf(ev0);
            den += w0;
            uint4 r0 = *((const uint4*)(g_lin1h + (size_t)s0 * F1) + lane);
            acc_row1(acc, r0, w0);
        }
        float inv = 1.f / (den + 1e-16f);
        const float4* bb = (const float4*)b1 + lane * 2;
        float4 b0 = bb[0], b4 = bb[1];
        float o[8];
        o[0] = acc[0] * inv + b0.x; o[1] = acc[1] * inv + b0.y;
        o[2] = acc[2] * inv + b0.z; o[3] = acc[3] * inv + b0.w;
        o[4] = acc[4] * inv + b4.x; o[5] = acc[5] * inv + b4.y;
        o[6] = acc[6] * inv + b4.z; o[7] = acc[7] * inv + b4.w;
        uint4 packed;
        *(__half2*)&packed.x = __floats2half2_rn(o[0], o[1]);
        *(__half2*)&packed.y = __floats2half2_rn(o[2], o[3]);
        *(__half2*)&packed.z = __floats2half2_rn(o[4], o[5]);
        *(__half2*)&packed.w = __floats2half2_rn(o[6], o[7]);
        *((uint4*)(g_h1h + (size_t)dst * F1) + lane) = packed;
        #pragma unroll
        for (int j = 0; j < 8; j++) { lsum[j] += o[j]; lsq[j] += o[j] * o[j]; }
    }
    __shared__ float ss[8 * F1];
    __shared__ float sqm[8 * F1];
    int fb = lane * 8;
    #pragma unroll
    for (int j = 0; j < 8; j++) { ss[wid * F1 + fb + j] = lsum[j]; sqm[wid * F1 + fb + j] = lsq[j]; }
    __syncthreads();
    int t = threadIdx.x;
    if (t < F1) {
        float s = 0.f, q = 0.f;
        #pragma unroll
        for (int w = 0; w < 8; w++) { s += ss[w * F1 + t]; q += sqm[w * F1 + t]; }
        atomicAdd(&g_sum1[t], s);
        atomicAdd(&g_sq1[t], q);
    }
}

__device__ __forceinline__ void acc_row2(float4& acc, const uint2& raw, float w) {
    float2 f;
    f = __half22float2(*(__half2*)&raw.x); acc.x += w * f.x; acc.y += w * f.y;
    f = __half22float2(*(__half2*)&raw.y); acc.z += w * f.x; acc.w += w * f.y;
}

__global__ void __launch_bounds__(256) agg2_csr(const float* __restrict__ b2) {
    int lane = threadIdx.x & 31;
    int wid = threadIdx.x >> 5;
    int sub = lane >> 4, sl = lane & 15;
    int ghw = (blockIdx.x * 8 + wid) * 2 + sub;
    int nhw = gridDim.x * 16;
    float lsum[4], lsq[4];
    #pragma unroll
    for (int j = 0; j < 4; j++) { lsum[j] = 0.f; lsq[j] = 0.f; }

    for (int dst = ghw; dst < NN; dst += nhw) {
        int beg = g_off[dst], end = g_off[dst + 1];
        float ad = g_ad2[dst];
        float4 acc = make_float4(0.f, 0.f, 0.f, 0.f);
        float den = 0.f;
        int e = beg;
        for (; e + 3 < end; e += 4) {
            int s0 = g_csr[e], s1 = g_csr[e + 1], s2 = g_csr[e + 2], s3 = g_csr[e + 3];
            float ev0 = g_as2[s0] + ad;
            float ev1 = g_as2[s1] + ad;
            float ev2 = g_as2[s2] + ad;
            float ev3 = g_as2[s3] + ad;
            ev0 = fmaxf(ev0, 0.2f * ev0);
            ev1 = fmaxf(ev1, 0.2f * ev1);
            ev2 = fmaxf(ev2, 0.2f * ev2);
            ev3 = fmaxf(ev3, 0.2f * ev3);
            float w0 = __expf(ev0), w1 = __expf(ev1), w2 = __expf(ev2), w3 = __expf(ev3);
            den += (w0 + w1) + (w2 + w3);
            uint2 r0 = *((const uint2*)(g_lin2h + (size_t)s0 * F2) + sl);
            uint2 r1 = *((const uint2*)(g_lin2h + (size_t)s1 * F2) + sl);
            uint2 r2 = *((const uint2*)(g_lin2h + (size_t)s2 * F2) + sl);
            uint2 r3 = *((const uint2*)(g_lin2h + (size_t)s3 * F2) + sl);
            acc_row2(acc, r0, w0); acc_row2(acc, r1, w1);
            acc_row2(acc, r2, w2); acc_row2(acc, r3, w3);
        }
        for (; e < end; e++) {
            int s0 = g_csr[e];
            float ev0 = g_as2[s0] + ad;
            ev0 = fmaxf(ev0, 0.2f * ev0);
            float w0 = __expf(ev0);
            den += w0;
            uint2 r0 = *((const uint2*)(g_lin2h + (size_t)s0 * F2) + sl);
            acc_row2(acc, r0, w0);
        }
        float inv = 1.f / (den + 1e-16f);
        float4 bb = ((const float4*)b2)[sl];
        float o0 = acc.x * inv + bb.x, o1 = acc.y * inv + bb.y;
        float o2 = acc.z * inv + bb.z, o3 = acc.w * inv + bb.w;
        uint2 packed;
        *(__half2*)&packed.x = __floats2half2_rn(o0, o1);
        *(__half2*)&packed.y = __floats2half2_rn(o2, o3);
        *((uint2*)(g_h2h + (size_t)dst * F2) + sl) = packed;
        lsum[0] += o0; lsum[1] += o1; lsum[2] += o2; lsum[3] += o3;
        lsq[0] += o0 * o0; lsq[1] += o1 * o1; lsq[2] += o2 * o2; lsq[3] += o3 * o3;
    }
    #pragma unroll
    for (int j = 0; j < 4; j++) {
        lsum[j] += __shfl_down_sync(0xffffffffu, lsum[j], 16);
        lsq[j]  += __shfl_down_sync(0xffffffffu, lsq[j], 16);
    }
    __shared__ float ss[8 * F2];
    __shared__ float sqm[8 * F2];
    if (lane < 16) {
        #pragma unroll
        for (int j = 0; j < 4; j++) {
            ss[wid * F2 + sl * 4 + j] = lsum[j];
            sqm[wid * F2 + sl * 4 + j] = lsq[j];
        }
    }
    __syncthreads();
    int t = threadIdx.x;
    if (t < F2) {
        float s = 0.f, q = 0.f;
        #pragma unroll
        for (int w = 0; w < 8; w++) { s += ss[w * F2 + t]; q += sqm[w * F2 + t]; }
        atomicAdd(&g_sum2[t], s);
        atomicAdd(&g_sq2[t], q);
    }
}

// ---------------- final BN apply (in-block finalize) ----------------
__global__ void bn3_apply(float* __restrict__ out,
                          const float* __restrict__ gamma, const float* __restrict__ beta) {
    __shared__ float s_sc[IND], s_sh[IND];
    int t = threadIdx.x;
    if (t < IND) {
        float mean = g_sum3[t] * (1.0f / NN);
        float var = fmaxf(g_sq3[t] * (1.0f / NN) - mean * mean, 0.f);
        float sc = gamma[t] * rsqrtf(var + 1e-5f);
        s_sc[t] = sc;
        s_sh[t] = beta[t] - mean * sc;
    }
    __syncthreads();
    int i = blockIdx.x * 256 + t;
    if (i >= NN * IND / 4) return;
    int cb = (i & 31) * 4;
    float4 v = ((float4*)out)[i];
    v.x = v.x * s_sc[cb + 0] + s_sh[cb + 0];
    v.y = v.y * s_sc[cb + 1] + s_sh[cb + 1];
    v.z = v.z * s_sc[cb + 2] + s_sh[cb + 2];
    v.w = v.w * s_sc[cb + 3] + s_sh[cb + 3];
    ((float4*)out)[i] = v;
}

// ---------------- launch ----------------
extern "C" void kernel_launch(void* const* d_in, const int* in_sizes, int n_in,
                              void* d_out, int out_size)
{
    const float* x   = (const float*)d_in[0];
    const int*   ei  = (const int*)d_in[1];
    const float* W1  = (const float*)d_in[2];
    const float* a1s = (const float*)d_in[3];
    const float* a1d = (const float*)d_in[4];
    const float* b1  = (const float*)d_in[5];
    const float* W2  = (const float*)d_in[6];
    const float* a2s = (const float*)d_in[7];
    const float* a2d = (const float*)d_in[8];
    const float* b2  = (const float*)d_in[9];
    const float* Wp  = (const float*)d_in[10];
    const float* bp  = (const float*)d_in[11];
    const float* g1  = (const float*)d_in[12];
    const float* be1 = (const float*)d_in[13];
    const float* g2  = (const float*)d_in[14];
    const float* be2 = (const float*)d_in[15];
    const float* g3  = (const float*)d_in[16];
    const float* be3 = (const float*)d_in[17];
    float* out = (float*)d_out;

    void *p_lin1h, *p_lin2h, *p_h1h, *p_h2h;
    float *p_sum1, *p_sq1, *p_sum2, *p_sq2, *p_sum3, *p_sq3;
    float *p_as1, *p_ad1, *p_as2, *p_ad2;
    cudaGetSymbolAddress(&p_lin1h, g_lin1h);
    cudaGetSymbolAddress(&p_lin2h, g_lin2h);
    cudaGetSymbolAddress(&p_h1h, g_h1h);
    cudaGetSymbolAddress(&p_h2h, g_h2h);
    cudaGetSymbolAddress((void**)&p_sum1, g_sum1);
    cudaGetSymbolAddress((void**)&p_sq1, g_sq1);
    cudaGetSymbolAddress((void**)&p_sum2, g_sum2);
    cudaGetSymbolAddress((void**)&p_sq2, g_sq2);
    cudaGetSymbolAddress((void**)&p_sum3, g_sum3);
    cudaGetSymbolAddress((void**)&p_sq3, g_sq3);
    cudaGetSymbolAddress((void**)&p_as1, g_as1);
    cudaGetSymbolAddress((void**)&p_ad1, g_ad1);
    cudaGetSymbolAddress((void**)&p_as2, g_as2);
    cudaGetSymbolAddress((void**)&p_ad2, g_ad2);

    static cudaStream_t s2 = nullptr;
    static cudaEvent_t evFork = nullptr, evJoin = nullptr;
    if (!s2) {
        cudaStreamCreateWithFlags(&s2, cudaStreamNonBlocking);
        cudaEventCreateWithFlags(&evFork, cudaEventDisableTiming);
        cudaEventCreateWithFlags(&evJoin, cudaEventDisableTiming);
    }

    const int MBY = (NN + 127) / 128;   // 391

    // fork: CSR build on s2, concurrent with GEMM1 on the main stream.
    // Submission order keeps gemm1 as the 4th launch for ncu's capture window.
    cudaEventRecord(evFork, 0);
    cudaStreamWaitEvent(s2, evFork, 0);
    zero_k<<<SCAN_BLOCKS, 256, 0, s2>>>();                        // #1
    hist_k<<<(ETOT + 255) / 256, 256, 0, s2>>>(ei);               // #2
    scan_part<<<SCAN_BLOCKS, 256, 0, s2>>>();                     // #3

    // ---- layer 1: GEMM (float in, alpha fused, half out), 2 panels ---- #4
    gemm_bf16<2, false, false, true, false, false, true><<<dim3(F1 / 128, MBY), 256>>>(
        x, W1, nullptr, nullptr, nullptr, nullptr, nullptr,
        a1s, a1d, p_as1, p_ad1, nullptr, nullptr, p_lin1h, NN, F1, IND);

    scan_fix2<<<SCAN_BLOCKS, 256, 0, s2>>>();                     // #5
    scatter_k<<<(ETOT + 255) / 256, 256, 0, s2>>>(ei);            // #6
    cudaEventRecord(evJoin, s2);

    cudaStreamWaitEvent(0, evJoin, 0);
    agg1_csr<<<1564, 256>>>(b1);                                  // #7

    // ---- layer 2: GEMM (half in + BN1+ELU, alpha fused, half out), 1 panel ----
    gemm_bf16<1, true, false, true, false, true, true><<<dim3(F2 / 64, MBY), 256>>>(
        p_h1h, W2, nullptr, p_sum1, p_sq1, g1, be1,
        a2s, a2d, p_as2, p_ad2, nullptr, nullptr, p_lin2h, NN, F2, F1);
    agg2_csr<<<1564, 256>>>(b2);

    // ---- projection: GEMM (half in + BN2+ELU, bias, BN3 stats fused, float out), 2 panels ----
    gemm_bf16<2, true, true, false, true, true, false><<<dim3(IND / 128, MBY), 256>>>(
        p_h2h, Wp, bp, p_sum2, p_sq2, g2, be2,
        nullptr, nullptr, nullptr, nullptr, p_sum3, p_sq3, out, NN, IND, F2);

    bn3_apply<<<(NN * IND / 4 + 255) / 256, 256>>>(out, g3, be3);
}

// round 13
// speedup vs baseline: 1.2082x; 1.2082x over previous
#include <cuda_runtime.h>
#include <cuda_fp16.h>
#include <math.h>

#define NN 50000
#define EE 800000
#define ETOT 850000
#define IND 128
#define F1 256
#define H1N 4
#define F2 64
#define SCAN_BLOCKS 196

// ---------------- scratch (device globals; no allocation allowed) ----------------
__device__ __align__(16) __half g_lin1h[(size_t)NN * F1];
__device__ __align__(16) __half g_h1h[(size_t)NN * F1];
__device__ __align__(16) __half g_lin2h[(size_t)NN * F2];
__device__ __align__(16) __half g_h2h[(size_t)NN * F2];
__device__ float g_as1[NN * H1N], g_ad1[NN * H1N];
__device__ float g_as2[NN], g_ad2[NN];
__device__ int g_deg[NN], g_off[NN + 1], g_pos[NN], g_csr[ETOT];
__device__ int g_bsum[SCAN_BLOCKS];
__device__ float g_sum1[F1], g_sq1[F1], g_sum2[F2], g_sq2[F2], g_sum3[IND], g_sq3[IND];

// ---------------- helpers ----------------
__device__ __forceinline__ float elu_f(float v) { return v > 0.f ? v : expm1f(v); }

// bf16 hi/lo split of two floats, packed as bf16x2 (f0 -> low half, f1 -> high half)
__device__ __forceinline__ void split2_bf16(float f0, float f1, unsigned& hi, unsigned& lo) {
    asm("cvt.rn.bf16x2.f32 %0, %1, %2;" : "=r"(hi) : "f"(f1), "f"(f0));
    float h0 = __uint_as_float(hi << 16);
    float h1 = __uint_as_float(hi & 0xffff0000u);
    float r0 = f0 - h0, r1 = f1 - h1;
    asm("cvt.rn.bf16x2.f32 %0, %1, %2;" : "=r"(lo) : "f"(r1), "f"(r0));
}

__device__ __forceinline__ void mma_bf16(float* c, const unsigned* a, const unsigned* b) {
    asm volatile(
        "mma.sync.aligned.m16n8k16.row.col.f32.bf16.bf16.f32 "
        "{%0,%1,%2,%3},{%4,%5,%6,%7},{%8,%9},{%0,%1,%2,%3};"
        : "+f"(c[0]), "+f"(c[1]), "+f"(c[2]), "+f"(c[3])
        : "r"(a[0]), "r"(a[1]), "r"(a[2]), "r"(a[3]), "r"(b[0]), "r"(b[1]));
}

__device__ __forceinline__ void edge_sd(const int* ei, int e, int& s, int& d) {
    if (e < EE) { s = ei[e]; d = ei[EE + e]; } else { s = d = e - EE; }
}

// ---------------- init ----------------
__global__ void zero_k() {
    int i = blockIdx.x * 256 + threadIdx.x;
    if (i < NN) g_deg[i] = 0;
    if (blockIdx.x == 0) {
        int t = threadIdx.x;
        if (t < F1) { g_sum1[t] = 0.f; g_sq1[t] = 0.f; }
        if (t < F2) { g_sum2[t] = 0.f; g_sq2[t] = 0.f; }
        if (t < IND) { g_sum3[t] = 0.f; g_sq3[t] = 0.f; }
    }
}

// ---------------- counting sort: hist -> scan -> scatter ----------------
__global__ void hist_k(const int* __restrict__ ei) {
    int e = blockIdx.x * blockDim.x + threadIdx.x;
    if (e >= ETOT) return;
    int s, d; edge_sd(ei, e, s, d);
    atomicAdd(&g_deg[d], 1);
}

__global__ void scan_part() {
    __shared__ int sm[256];
    int t = threadIdx.x;
    int i = blockIdx.x * 256 + t;
    int v = (i < NN) ? g_deg[i] : 0;
    sm[t] = v; __syncthreads();
    #pragma unroll
    for (int off = 1; off < 256; off <<= 1) {
        int x = (t >= off) ? sm[t - off] : 0;
        __syncthreads();
        sm[t] += x; __syncthreads();
    }
    if (i < NN) g_off[i] = sm[t];
    if (t == 255) g_bsum[blockIdx.x] = sm[255];
}

__global__ void scan_fix2() {
    __shared__ int sb[256];
    int t = threadIdx.x;
    sb[t] = (t < SCAN_BLOCKS) ? g_bsum[t] : 0;
    __syncthreads();
    #pragma unroll
    for (int off = 1; off < 256; off <<= 1) {
        int x = (t >= off) ? sb[t - off] : 0;
        __syncthreads();
        sb[t] += x; __syncthreads();
    }
    int base = (blockIdx.x == 0) ? 0 : sb[blockIdx.x - 1];
    int i = blockIdx.x * 256 + t;
    if (i < NN) {
        int off = g_off[i] - g_deg[i] + base;
        g_off[i] = off;
        g_pos[i] = off;
    }
    if (i == 0) g_off[NN] = ETOT;
}

__global__ void scatter_k(const int* __restrict__ ei) {
    int e = blockIdx.x * blockDim.x + threadIdx.x;
    if (e >= ETOT) return;
    int s, d; edge_sd(ei, e, s, d);
    int p = atomicAdd(&g_pos[d], 1);
    g_csr[p] = s;
}

// ---------------- bf16x3 tensor-core GEMM, NP column panels per block ----------------
// Round-11 verified layout: separate hi/lo tiles, 2x LDS.32 per fragment pair.
template<int NP, bool PRE_BN, bool BIAS, bool ALPHA, bool BNSTAT, bool HALF_IN, bool HALF_OUT>
__global__ void __launch_bounds__(256)
gemm_bf16(const void* __restrict__ Av, const float* __restrict__ B,
          const float* __restrict__ bias,
          const float* __restrict__ psum, const float* __restrict__ psq,
          const float* __restrict__ pgamma, const float* __restrict__ pbeta,
          const float* __restrict__ avs, const float* __restrict__ avd,
          float* __restrict__ as_out, float* __restrict__ ad_out,
          float* __restrict__ bnsum_out, float* __restrict__ bnsq_out,
          void* __restrict__ Cv, int M, int N, int K)
{
    const int BM = 128, BN = 64, BK = 32, BKP = 16;
    __shared__ __align__(16) unsigned Ah[BM][BKP + 2];
    __shared__ __align__(16) unsigned Al[BM][BKP + 2];
    __shared__ __align__(16) unsigned Bh[NP][BKP][BN + 8];
    __shared__ __align__(16) unsigned Bl[NP][BKP][BN + 8];
    __shared__ float s_sc[256], s_sh[256];
    __shared__ float s_as[NP * BM], s_ad[NP * BM];
    __shared__ float s_bs[NP * BN], s_bq[NP * BN];
    int tid = threadIdx.x;
    int lane = tid & 31, wid = tid >> 5;
    int wm = wid & 3, wn = wid >> 2;
    int row0 = blockIdx.y * BM;
    int colBase = blockIdx.x * (NP * BN);
    int g = lane >> 2, tg = lane & 3;

    if (PRE_BN) {
        if (tid < K) {
            float mean = psum[tid] * (1.0f / NN);
            float var = fmaxf(psq[tid] * (1.0f / NN) - mean * mean, 0.f);
            float sc = pgamma[tid] * rsqrtf(var + 1e-5f);
            s_sc[tid] = sc;
            s_sh[tid] = pbeta[tid] - mean * sc;
        }
        __syncthreads();
    }
    if (ALPHA) {
        #pragma unroll
        for (int p = 0; p < NP; p++)
            if (tid < BM) { s_as[p * BM + tid] = 0.f; s_ad[p * BM + tid] = 0.f; }
    }
    if (BNSTAT && tid < NP * BN) { s_bs[tid] = 0.f; s_bq[tid] = 0.f; }

    float c[NP][2][4][4];
    #pragma unroll
    for (int p = 0; p < NP; p++)
        #pragma unroll
        for (int mt = 0; mt < 2; mt++)
            #pragma unroll
            for (int nt = 0; nt < 4; nt++)
                #pragma unroll
                for (int j = 0; j < 4; j++) c[p][mt][nt][j] = 0.f;

    for (int k0 = 0; k0 < K; k0 += BK) {
        if (HALF_IN) {
            const __half* Ahp = (const __half*)Av;
            #pragma unroll
            for (int i = 0; i < 2; i++) {
                int idx = i * 256 + tid;
                int r = idx >> 2, q = idx & 3;
                uint4 raw = make_uint4(0u, 0u, 0u, 0u);
                if (row0 + r < M)
                    raw = *(const uint4*)(Ahp + (size_t)(row0 + r) * K + k0 + q * 8);
                float f[8];
                float2 t2;
                t2 = __half22float2(*(__half2*)&raw.x); f[0] = t2.x; f[1] = t2.y;
                t2 = __half22float2(*(__half2*)&raw.y); f[2] = t2.x; f[3] = t2.y;
                t2 = __half22float2(*(__half2*)&raw.z); f[4] = t2.x; f[5] = t2.y;
                t2 = __half22float2(*(__half2*)&raw.w); f[6] = t2.x; f[7] = t2.y;
                if (PRE_BN) {
                    int b = k0 + q * 8;
                    #pragma unroll
                    for (int j = 0; j < 8; j++) f[j] = elu_f(f[j] * s_sc[b + j] + s_sh[b + j]);
                }
                #pragma unroll
                for (int j = 0; j < 4; j++) {
                    unsigned hi, lo;
                    split2_bf16(f[j * 2], f[j * 2 + 1], hi, lo);
                    Ah[r][q * 4 + j] = hi;
                    Al[r][q * 4 + j] = lo;
                }
            }
        } else {
            const float* Af = (const float*)Av;
            #pragma unroll
            for (int i = 0; i < 4; i++) {
                int idx = i * 256 + tid;
                int r = idx >> 3, q = idx & 7;
                float4 v = make_float4(0.f, 0.f, 0.f, 0.f);
                if (row0 + r < M)
                    v = *(const float4*)(Af + (size_t)(row0 + r) * K + k0 + q * 4);
                if (PRE_BN) {
                    int b = k0 + q * 4;
                    v.x = elu_f(v.x * s_sc[b + 0] + s_sh[b + 0]);
                    v.y = elu_f(v.y * s_sc[b + 1] + s_sh[b + 1]);
                    v.z = elu_f(v.z * s_sc[b + 2] + s_sh[b + 2]);
                    v.w = elu_f(v.w * s_sc[b + 3] + s_sh[b + 3]);
                }
                unsigned h0, l0, h1, l1;
                split2_bf16(v.x, v.y, h0, l0);
                split2_bf16(v.z, v.w, h1, l1);
                Ah[r][q * 2 + 0] = h0; Ah[r][q * 2 + 1] = h1;
                Al[r][q * 2 + 0] = l0; Al[r][q * 2 + 1] = l1;
            }
        }
        {
            int kp = tid >> 4;
            int cq = (tid & 15) * 4;
            #pragma unroll
            for (int p = 0; p < NP; p++) {
                int cb = colBase + p * BN + cq;
                float4 v0 = *(const float4*)(B + (size_t)(k0 + 2 * kp) * N + cb);
                float4 v1 = *(const float4*)(B + (size_t)(k0 + 2 * kp + 1) * N + cb);
                unsigned h, l;
                split2_bf16(v0.x, v1.x, h, l); Bh[p][kp][cq + 0] = h; Bl[p][kp][cq + 0] = l;
                split2_bf16(v0.y, v1.y, h, l); Bh[p][kp][cq + 1] = h; Bl[p][kp][cq + 1] = l;
                split2_bf16(v0.z, v1.z, h, l); Bh[p][kp][cq + 2] = h; Bl[p][kp][cq + 2] = l;
                split2_bf16(v0.w, v1.w, h, l); Bh[p][kp][cq + 3] = h; Bl[p][kp][cq + 3] = l;
            }
        }
        __syncthreads();

        #pragma unroll
        for (int kk = 0; kk < 2; kk++) {
            unsigned ahi[2][4], alo[2][4];
            #pragma unroll
            for (int mt = 0; mt < 2; mt++) {
                int rb = wm * 32 + mt * 16 + g;
                int kp = kk * 8 + tg;
                ahi[mt][0] = Ah[rb][kp];          alo[mt][0] = Al[rb][kp];
                ahi[mt][1] = Ah[rb + 8][kp];      alo[mt][1] = Al[rb + 8][kp];
                ahi[mt][2] = Ah[rb][kp + 4];      alo[mt][2] = Al[rb][kp + 4];
                ahi[mt][3] = Ah[rb + 8][kp + 4];  alo[mt][3] = Al[rb + 8][kp + 4];
            }
            #pragma unroll
            for (int p = 0; p < NP; p++) {
                unsigned bhi[4][2], blo[4][2];
                #pragma unroll
                for (int nt = 0; nt < 4; nt++) {
                    int cb = wn * 32 + nt * 8 + g;
                    int kp = kk * 8 + tg;
                    bhi[nt][0] = Bh[p][kp][cb];
                    bhi[nt][1] = Bh[p][kp + 4][cb];
                    blo[nt][0] = Bl[p][kp][cb];
                    blo[nt][1] = Bl[p][kp + 4][cb];
                }
                #pragma unroll
                for (int mt = 0; mt < 2; mt++)
                    #pragma unroll
                    for (int nt = 0; nt < 4; nt++) {
                        mma_bf16(c[p][mt][nt], ahi[mt], blo[nt]);
                        mma_bf16(c[p][mt][nt], alo[mt], bhi[nt]);
                        mma_bf16(c[p][mt][nt], ahi[mt], bhi[nt]);
                    }
            }
        }
        __syncthreads();
    }

    float* Cf = (float*)Cv;
    __half* Ch = (__half*)Cv;

    #pragma unroll
    for (int p = 0; p < NP; p++) {
        float pas[2][2], pad[2][2];
        float colsum[8], colsq[8];
        if (ALPHA) {
            #pragma unroll
            for (int a = 0; a < 2; a++)
                #pragma unroll
                for (int b = 0; b < 2; b++) { pas[a][b] = 0.f; pad[a][b] = 0.f; }
        }
        if (BNSTAT) {
            #pragma unroll
            for (int j = 0; j < 8; j++) { colsum[j] = 0.f; colsq[j] = 0.f; }
        }

        #pragma unroll
        for (int mt = 0; mt < 2; mt++)
            #pragma unroll
            for (int nt = 0; nt < 4; nt++) {
                int r = row0 + wm * 32 + mt * 16 + g;
                int cc = colBase + p * BN + wn * 32 + nt * 8 + tg * 2;
                float v00 = c[p][mt][nt][0], v01 = c[p][mt][nt][1];
                float v10 = c[p][mt][nt][2], v11 = c[p][mt][nt][3];
                if (BIAS) {
                    float bx = bias[cc], by = bias[cc + 1];
                    v00 += bx; v01 += by; v10 += bx; v11 += by;
                }
                if (ALPHA) {
                    float s0 = avs[cc], s1 = avs[cc + 1];
                    float d0 = avd[cc], d1 = avd[cc + 1];
                    pas[mt][0] += v00 * s0 + v01 * s1;
                    pad[mt][0] += v00 * d0 + v01 * d1;
                    pas[mt][1] += v10 * s0 + v11 * s1;
                    pad[mt][1] += v10 * d0 + v11 * d1;
                }
                if (BNSTAT) {
                    if (r < M)     { colsum[nt * 2] += v00; colsq[nt * 2] += v00 * v00;
                                     colsum[nt * 2 + 1] += v01; colsq[nt * 2 + 1] += v01 * v01; }
                    if (r + 8 < M) { colsum[nt * 2] += v10; colsq[nt * 2] += v10 * v10;
                                     colsum[nt * 2 + 1] += v11; colsq[nt * 2 + 1] += v11 * v11; }
                }
                if (HALF_OUT) {
                    if (r < M)     *(__half2*)(Ch + (size_t)r * N + cc) = __floats2half2_rn(v00, v01);
                    if (r + 8 < M) *(__half2*)(Ch + (size_t)(r + 8) * N + cc) = __floats2half2_rn(v10, v11);
                } else {
                    if (r < M)     *(float2*)(Cf + (size_t)r * N + cc) = make_float2(v00, v01);
                    if (r + 8 < M) *(float2*)(Cf + (size_t)(r + 8) * N + cc) = make_float2(v10, v11);
                }
            }

        if (ALPHA) {
            #pragma unroll
            for (int mt = 0; mt < 2; mt++)
                #pragma unroll
                for (int ro = 0; ro < 2; ro++) {
                    float vs = pas[mt][ro], vd = pad[mt][ro];
                    vs += __shfl_down_sync(0xffffffffu, vs, 2);
                    vs += __shfl_down_sync(0xffffffffu, vs, 1);
                    vd += __shfl_down_sync(0xffffffffu, vd, 2);
                    vd += __shfl_down_sync(0xffffffffu, vd, 1);
                    if (tg == 0) {
                        int rl = wm * 32 + mt * 16 + ro * 8 + g;
                        atomicAdd(&s_as[p * BM + rl], vs);
                        atomicAdd(&s_ad[p * BM + rl], vd);
                    }
                }
        }
        if (BNSTAT) {
            #pragma unroll
            for (int j = 0; j < 8; j++) {
                float v = colsum[j], q = colsq[j];
                v += __shfl_down_sync(0xffffffffu, v, 16);
                v += __shfl_down_sync(0xffffffffu, v, 8);
                v += __shfl_down_sync(0xffffffffu, v, 4);
                q += __shfl_down_sync(0xffffffffu, q, 16);
                q += __shfl_down_sync(0xffffffffu, q, 8);
                q += __shfl_down_sync(0xffffffffu, q, 4);
                if (lane < 4) {
                    int cb = wn * 32 + (j >> 1) * 8 + tg * 2 + (j & 1);
                    atomicAdd(&s_bs[p * BN + cb], v);
                    atomicAdd(&s_bq[p * BN + cb], q);
                }
            }
        }
    }
    if (ALPHA || BNSTAT) {
        __syncthreads();
        if (ALPHA && tid < BM) {
            int r = row0 + tid;
            if (r < M) {
                int nh = gridDim.x * NP;
                #pragma unroll
                for (int p = 0; p < NP; p++) {
                    as_out[(size_t)r * nh + blockIdx.x * NP + p] = s_as[p * BM + tid];
                    ad_out[(size_t)r * nh + blockIdx.x * NP + p] = s_ad[p * BM + tid];
                }
            }
        }
        if (BNSTAT && tid < NP * BN) {
            atomicAdd(&bnsum_out[colBase + tid], s_bs[tid]);
            atomicAdd(&bnsq_out[colBase + tid], s_bq[tid]);
        }
    }
}

// ---------------- CSR aggregation (softmax + weighted sum + bias + BN stats) ----------------
__device__ __forceinline__ void acc_row1(float* acc, const uint4& raw, float w) {
    float2 f;
    f = __half22float2(*(__half2*)&raw.x); acc[0] += w * f.x; acc[1] += w * f.y;
    f = __half22float2(*(__half2*)&raw.y); acc[2] += w * f.x; acc[3] += w * f.y;
    f = __half22float2(*(__half2*)&raw.z); acc[4] += w * f.x; acc[5] += w * f.y;
    f = __half22float2(*(__half2*)&raw.w); acc[6] += w * f.x; acc[7] += w * f.y;
}

__global__ void __launch_bounds__(256) agg1_csr(const float* __restrict__ b1) {
    int lane = threadIdx.x & 31;
    int wid = threadIdx.x >> 5;
    int gw = blockIdx.x * 8 + wid;
    int nw = gridDim.x * 8;
    int h = lane >> 3;
    float lsum[8], lsq[8];
    #pragma unroll
    for (int j = 0; j < 8; j++) { lsum[j] = 0.f; lsq[j] = 0.f; }

    for (int dst = gw; dst < NN; dst += nw) {
        int beg = g_off[dst], end = g_off[dst + 1];
        float ad = g_ad1[dst * 4 + h];
        float acc[8];
        #pragma unroll
        for (int j = 0; j < 8; j++) acc[j] = 0.f;
        float den = 0.f;
        int e = beg;
        for (; e + 3 < end; e += 4) {
            int s0 = g_csr[e], s1 = g_csr[e + 1], s2 = g_csr[e + 2], s3 = g_csr[e + 3];
            float ev0 = g_as1[s0 * 4 + h] + ad;
            float ev1 = g_as1[s1 * 4 + h] + ad;
            float ev2 = g_as1[s2 * 4 + h] + ad;
            float ev3 = g_as1[s3 * 4 + h] + ad;
            ev0 = fmaxf(ev0, 0.2f * ev0);
            ev1 = fmaxf(ev1, 0.2f * ev1);
            ev2 = fmaxf(ev2, 0.2f * ev2);
            ev3 = fmaxf(ev3, 0.2f * ev3);
            float w0 = __expf(ev0), w1 = __expf(ev1), w2 = __expf(ev2), w3 = __expf(ev3);
            den += (w0 + w1) + (w2 + w3);
            uint4 r0 = *((const uint4*)(g_lin1h + (size_t)s0 * F1) + lane);
            uint4 r1 = *((const uint4*)(g_lin1h + (size_t)s1 * F1) + lane);
            uint4 r2 = *((const uint4*)(g_lin1h + (size_t)s2 * F1) + lane);
            uint4 r3 = *((const uint4*)(g_lin1h + (size_t)s3 * F1) + lane);
            acc_row1(acc, r0, w0); acc_row1(acc, r1, w1);
            acc_row1(acc, r2, w2); acc_row1(acc, r3, w3);
        }
        for (; e < end; e++) {
            int s0 = g_csr[e];
            float ev0 = g_as1[s0 * 4 + h] + ad;
            ev0 = fmaxf(ev0, 0.2f * ev0);
            float w0 = __expf(ev0);
            den += w0;
            uint4 r0 = *((const uint4*)(g_lin1h + (size_t)s0 * F1) + lane);
            acc_row1(acc, r0, w0);
        }
        float inv = 1.f / (den + 1e-16f);
        const float4* bb = (const float4*)b1 + lane * 2;
        float4 b0 = bb[0], b4 = bb[1];
        float o[8];
        o[0] = acc[0] * inv + b0.x; o[1] = acc[1] * inv + b0.y;
        o[2] = acc[2] * inv + b0.z; o[3] = acc[3] * inv + b0.w;
        o[4] = acc[4] * inv + b4.x; o[5] = acc[5] * inv + b4.y;
        o[6] = acc[6] * inv + b4.z; o[7] = acc[7] * inv + b4.w;
        uint4 packed;
        *(__half2*)&packed.x = __floats2half2_rn(o[0], o[1]);
        *(__half2*)&packed.y = __floats2half2_rn(o[2], o[3]);
        *(__half2*)&packed.z = __floats2half2_rn(o[4], o[5]);
        *(__half2*)&packed.w = __floats2half2_rn(o[6], o[7]);
        *((uint4*)(g_h1h + (size_t)dst * F1) + lane) = packed;
        #pragma unroll
        for (int j = 0; j < 8; j++) { lsum[j] += o[j]; lsq[j] += o[j] * o[j]; }
    }
    __shared__ float ss[8 * F1];
    __shared__ float sqm[8 * F1];
    int fb = lane * 8;
    #pragma unroll
    for (int j = 0; j < 8; j++) { ss[wid * F1 + fb + j] = lsum[j]; sqm[wid * F1 + fb + j] = lsq[j]; }
    __syncthreads();
    int t = threadIdx.x;
    if (t < F1) {
        float s = 0.f, q = 0.f;
        #pragma unroll
        for (int w = 0; w < 8; w++) { s += ss[w * F1 + t]; q += sqm[w * F1 + t]; }
        atomicAdd(&g_sum1[t], s);
        atomicAdd(&g_sq1[t], q);
    }
}

__device__ __forceinline__ void acc_row2(float4& acc, const uint2& raw, float w) {
    float2 f;
    f = __half22float2(*(__half2*)&raw.x); acc.x += w * f.x; acc.y += w * f.y;
    f = __half22float2(*(__half2*)&raw.y); acc.z += w * f.x; acc.w += w * f.y;
}

__global__ void __launch_bounds__(256) agg2_csr(const float* __restrict__ b2) {
    int lane = threadIdx.x & 31;
    int wid = threadIdx.x >> 5;
    int sub = lane >> 4, sl = lane & 15;
    int ghw = (blockIdx.x * 8 + wid) * 2 + sub;
    int nhw = gridDim.x * 16;
    float lsum[4], lsq[4];
    #pragma unroll
    for (int j = 0; j < 4; j++) { lsum[j] = 0.f; lsq[j] = 0.f; }

    for (int dst = ghw; dst < NN; dst += nhw) {
        int beg = g_off[dst], end = g_off[dst + 1];
        float ad = g_ad2[dst];
        float4 acc = make_float4(0.f, 0.f, 0.f, 0.f);
        float den = 0.f;
        int e = beg;
        for (; e + 3 < end; e += 4) {
            int s0 = g_csr[e], s1 = g_csr[e + 1], s2 = g_csr[e + 2], s3 = g_csr[e + 3];
            float ev0 = g_as2[s0] + ad;
            float ev1 = g_as2[s1] + ad;
            float ev2 = g_as2[s2] + ad;
            float ev3 = g_as2[s3] + ad;
            ev0 = fmaxf(ev0, 0.2f * ev0);
            ev1 = fmaxf(ev1, 0.2f * ev1);
            ev2 = fmaxf(ev2, 0.2f * ev2);
            ev3 = fmaxf(ev3, 0.2f * ev3);
            float w0 = __expf(ev0), w1 = __expf(ev1), w2 = __expf(ev2), w3 = __expf(ev3);
            den += (w0 + w1) + (w2 + w3);
            uint2 r0 = *((const uint2*)(g_lin2h + (size_t)s0 * F2) + sl);
            uint2 r1 = *((const uint2*)(g_lin2h + (size_t)s1 * F2) + sl);
            uint2 r2 = *((const uint2*)(g_lin2h + (size_t)s2 * F2) + sl);
            uint2 r3 = *((const uint2*)(g_lin2h + (size_t)s3 * F2) + sl);
            acc_row2(acc, r0, w0); acc_row2(acc, r1, w1);
            acc_row2(acc, r2, w2); acc_row2(acc, r3, w3);
        }
        for (; e < end; e++) {
            int s0 = g_csr[e];
            float ev0 = g_as2[s0] + ad;
            ev0 = fmaxf(ev0, 0.2f * ev0);
            float w0 = __expf(ev0);
            den += w0;
            uint2 r0 = *((const uint2*)(g_lin2h + (size_t)s0 * F2) + sl);
            acc_row2(acc, r0, w0);
        }
        float inv = 1.f / (den + 1e-16f);
        float4 bb = ((const float4*)b2)[sl];
        float o0 = acc.x * inv + bb.x, o1 = acc.y * inv + bb.y;
        float o2 = acc.z * inv + bb.z, o3 = acc.w * inv + bb.w;
        uint2 packed;
        *(__half2*)&packed.x = __floats2half2_rn(o0, o1);
        *(__half2*)&packed.y = __floats2half2_rn(o2, o3);
        *((uint2*)(g_h2h + (size_t)dst * F2) + sl) = packed;
        lsum[0] += o0; lsum[1] += o1; lsum[2] += o2; lsum[3] += o3;
        lsq[0] += o0 * o0; lsq[1] += o1 * o1; lsq[2] += o2 * o2; lsq[3] += o3 * o3;
    }
    #pragma unroll
    for (int j = 0; j < 4; j++) {
        lsum[j] += __shfl_down_sync(0xffffffffu, lsum[j], 16);
        lsq[j]  += __shfl_down_sync(0xffffffffu, lsq[j], 16);
    }
    __shared__ float ss[8 * F2];
    __shared__ float sqm[8 * F2];
    if (lane < 16) {
        #pragma unroll
        for (int j = 0; j < 4; j++) {
            ss[wid * F2 + sl * 4 + j] = lsum[j];
            sqm[wid * F2 + sl * 4 + j] = lsq[j];
        }
    }
    __syncthreads();
    int t = threadIdx.x;
    if (t < F2) {
        float s = 0.f, q = 0.f;
        #pragma unroll
        for (int w = 0; w < 8; w++) { s += ss[w * F2 + t]; q += sqm[w * F2 + t]; }
        atomicAdd(&g_sum2[t], s);
        atomicAdd(&g_sq2[t], q);
    }
}

// ---------------- final BN apply (in-block finalize) ----------------
__global__ void bn3_apply(float* __restrict__ out,
                          const float* __restrict__ gamma, const float* __restrict__ beta) {
    __shared__ float s_sc[IND], s_sh[IND];
    int t = threadIdx.x;
    if (t < IND) {
        float mean = g_sum3[t] * (1.0f / NN);
        float var = fmaxf(g_sq3[t] * (1.0f / NN) - mean * mean, 0.f);
        float sc = gamma[t] * rsqrtf(var + 1e-5f);
        s_sc[t] = sc;
        s_sh[t] = beta[t] - mean * sc;
    }
    __syncthreads();
    int i = blockIdx.x * 256 + t;
    if (i >= NN * IND / 4) return;
    int cb = (i & 31) * 4;
    float4 v = ((float4*)out)[i];
    v.x = v.x * s_sc[cb + 0] + s_sh[cb + 0];
    v.y = v.y * s_sc[cb + 1] + s_sh[cb + 1];
    v.z = v.z * s_sc[cb + 2] + s_sh[cb + 2];
    v.w = v.w * s_sc[cb + 3] + s_sh[cb + 3];
    ((float4*)out)[i] = v;
}

// ---------------- launch ----------------
extern "C" void kernel_launch(void* const* d_in, const int* in_sizes, int n_in,
                              void* d_out, int out_size)
{
    const float* x   = (const float*)d_in[0];
    const int*   ei  = (const int*)d_in[1];
    const float* W1  = (const float*)d_in[2];
    const float* a1s = (const float*)d_in[3];
    const float* a1d = (const float*)d_in[4];
    const float* b1  = (const float*)d_in[5];
    const float* W2  = (const float*)d_in[6];
    const float* a2s = (const float*)d_in[7];
    const float* a2d = (const float*)d_in[8];
    const float* b2  = (const float*)d_in[9];
    const float* Wp  = (const float*)d_in[10];
    const float* bp  = (const float*)d_in[11];
    const float* g1  = (const float*)d_in[12];
    const float* be1 = (const float*)d_in[13];
    const float* g2  = (const float*)d_in[14];
    const float* be2 = (const float*)d_in[15];
    const float* g3  = (const float*)d_in[16];
    const float* be3 = (const float*)d_in[17];
    float* out = (float*)d_out;

    void *p_lin1h, *p_lin2h, *p_h1h, *p_h2h;
    float *p_sum1, *p_sq1, *p_sum2, *p_sq2, *p_sum3, *p_sq3;
    float *p_as1, *p_ad1, *p_as2, *p_ad2;
    cudaGetSymbolAddress(&p_lin1h, g_lin1h);
    cudaGetSymbolAddress(&p_lin2h, g_lin2h);
    cudaGetSymbolAddress(&p_h1h, g_h1h);
    cudaGetSymbolAddress(&p_h2h, g_h2h);
    cudaGetSymbolAddress((void**)&p_sum1, g_sum1);
    cudaGetSymbolAddress((void**)&p_sq1, g_sq1);
    cudaGetSymbolAddress((void**)&p_sum2, g_sum2);
    cudaGetSymbolAddress((void**)&p_sq2, g_sq2);
    cudaGetSymbolAddress((void**)&p_sum3, g_sum3);
    cudaGetSymbolAddress((void**)&p_sq3, g_sq3);
    cudaGetSymbolAddress((void**)&p_as1, g_as1);
    cudaGetSymbolAddress((void**)&p_ad1, g_ad1);
    cudaGetSymbolAddress((void**)&p_as2, g_as2);
    cudaGetSymbolAddress((void**)&p_ad2, g_ad2);

    static cudaStream_t s2 = nullptr;
    static cudaEvent_t evFork = nullptr, evJoin = nullptr;
    if (!s2) {
        cudaStreamCreateWithFlags(&s2, cudaStreamNonBlocking);
        cudaEventCreateWithFlags(&evFork, cudaEventDisableTiming);
        cudaEventCreateWithFlags(&evJoin, cudaEventDisableTiming);
    }

    const int MBY = (NN + 127) / 128;   // 391

    // fork: CSR build on s2, concurrent with GEMM1 on the main stream.
    // Submission order keeps gemm1 as the 4th launch for ncu's capture window.
    cudaEventRecord(evFork, 0);
    cudaStreamWaitEvent(s2, evFork, 0);
    zero_k<<<SCAN_BLOCKS, 256, 0, s2>>>();                        // #1
    hist_k<<<(ETOT + 255) / 256, 256, 0, s2>>>(ei);               // #2
    scan_part<<<SCAN_BLOCKS, 256, 0, s2>>>();                     // #3

    // ---- layer 1: GEMM (float in, alpha fused, half out), 2 panels ---- #4
    gemm_bf16<2, false, false, true, false, false, true><<<dim3(F1 / 128, MBY), 256>>>(
        x, W1, nullptr, nullptr, nullptr, nullptr, nullptr,
        a1s, a1d, p_as1, p_ad1, nullptr, nullptr, p_lin1h, NN, F1, IND);

    scan_fix2<<<SCAN_BLOCKS, 256, 0, s2>>>();                     // #5
    scatter_k<<<(ETOT + 255) / 256, 256, 0, s2>>>(ei);            // #6
    cudaEventRecord(evJoin, s2);

    cudaStreamWaitEvent(0, evJoin, 0);
    agg1_csr<<<1564, 256>>>(b1);                                  // #7

    // ---- layer 2: GEMM (half in + BN1+ELU, alpha fused, half out), 1 panel ----
    gemm_bf16<1, true, false, true, false, true, true><<<dim3(F2 / 64, MBY), 256>>>(
        p_h1h, W2, nullptr, p_sum1, p_sq1, g1, be1,
        a2s, a2d, p_as2, p_ad2, nullptr, nullptr, p_lin2h, NN, F2, F1);
    agg2_csr<<<1564, 256>>>(b2);

    // ---- projection: GEMM (half in + BN2+ELU, bias, BN3 stats fused, float out), 2 panels ----
    gemm_bf16<2, true, true, false, true, true, false><<<dim3(IND / 128, MBY), 256>>>(
        p_h2h, Wp, bp, p_sum2, p_sq2, g2, be2,
        nullptr, nullptr, nullptr, nullptr, p_sum3, p_sq3, out, NN, IND, F2);

    bn3_apply<<<(NN * IND / 4 + 255) / 256, 256>>>(out, g3, be3);
}